// round 2
// baseline (speedup 1.0000x reference)
#include <cuda_runtime.h>

#define E_ 16
#define T_ 256
#define H_ 2048
#define I_ 1024

// 16 MB intermediate: h[e,t,i] = silu(gate) * up
__device__ float g_hbuf[E_ * T_ * I_];

// ---------------------------------------------------------------------------
// Kernel A: for each expert e, tile of g = X @ Wg^T and u = X @ Wu^T computed
// together (shared X tile), h = silu(g)*u written to scratch.
// grid = (I/64, T/128, E), block = 256 threads.
// Tile: M=128 (tokens) x N=64 (I dim), K-step 32 over H.
// Each thread: 8x4 microtile for BOTH gemms (64 accumulators).
// ---------------------------------------------------------------------------
__global__ __launch_bounds__(256)
void moe_gateup_kernel(const float* __restrict__ x,
                       const float* __restrict__ wg,
                       const float* __restrict__ wu)
{
    // K-major SMEM, padded rows (row strides are multiples of 16B -> LDS.128)
    __shared__ float Xs[32 * 132];   // [k][m], m padded 128->132
    __shared__ float Gs[32 * 68];    // [k][n], n padded 64->68
    __shared__ float Us[32 * 68];

    const int e    = blockIdx.z;
    const int row0 = blockIdx.y * 128;   // token tile
    const int col0 = blockIdx.x * 64;    // I tile
    const int tid  = threadIdx.x;
    const int tx   = tid & 15;           // N dir: 16 threads x 4 cols
    const int ty   = tid >> 4;           // M dir: 16 threads x 8 rows

    const float* wg_e = wg + (size_t)e * I_ * H_;
    const float* wu_e = wu + (size_t)e * I_ * H_;

    float accg[8][4];
    float accu[8][4];
#pragma unroll
    for (int m = 0; m < 8; ++m)
#pragma unroll
        for (int n = 0; n < 4; ++n) { accg[m][n] = 0.f; accu[m][n] = 0.f; }

    for (int kk = 0; kk < H_; kk += 32) {
        // X tile: 128 rows x 32 k  (4096 elems, 16 per thread)
#pragma unroll
        for (int i = tid; i < 128 * 32; i += 256) {
            int m = i >> 5, k = i & 31;
            Xs[k * 132 + m] = x[(size_t)(row0 + m) * H_ + kk + k];
        }
        // W tiles: 64 rows x 32 k (2048 elems, 8 per thread each)
#pragma unroll
        for (int i = tid; i < 64 * 32; i += 256) {
            int n = i >> 5, k = i & 31;
            size_t go = (size_t)(col0 + n) * H_ + kk + k;
            Gs[k * 68 + n] = wg_e[go];
            Us[k * 68 + n] = wu_e[go];
        }
        __syncthreads();

#pragma unroll
        for (int k = 0; k < 32; ++k) {
            float a[8], bg[4], bu[4];
            const float4 a0 = *reinterpret_cast<const float4*>(&Xs[k * 132 + ty * 8]);
            const float4 a1 = *reinterpret_cast<const float4*>(&Xs[k * 132 + ty * 8 + 4]);
            a[0]=a0.x; a[1]=a0.y; a[2]=a0.z; a[3]=a0.w;
            a[4]=a1.x; a[5]=a1.y; a[6]=a1.z; a[7]=a1.w;
            const float4 g4 = *reinterpret_cast<const float4*>(&Gs[k * 68 + tx * 4]);
            const float4 u4 = *reinterpret_cast<const float4*>(&Us[k * 68 + tx * 4]);
            bg[0]=g4.x; bg[1]=g4.y; bg[2]=g4.z; bg[3]=g4.w;
            bu[0]=u4.x; bu[1]=u4.y; bu[2]=u4.z; bu[3]=u4.w;
#pragma unroll
            for (int m = 0; m < 8; ++m)
#pragma unroll
                for (int n = 0; n < 4; ++n) {
                    accg[m][n] = fmaf(a[m], bg[n], accg[m][n]);
                    accu[m][n] = fmaf(a[m], bu[n], accu[m][n]);
                }
        }
        __syncthreads();
    }

    // Epilogue: h = silu(g) * u -> scratch (float4 stores)
    const int row = row0 + ty * 8;
    const int col = col0 + tx * 4;
    float* hp = g_hbuf + ((size_t)e * T_ + row) * I_ + col;
#pragma unroll
    for (int m = 0; m < 8; ++m) {
        float4 v;
        float r[4];
#pragma unroll
        for (int n = 0; n < 4; ++n) {
            float g = accg[m][n];
            float s = g / (1.0f + __expf(-g));   // silu
            r[n] = s * accu[m][n];
        }
        v.x = r[0]; v.y = r[1]; v.z = r[2]; v.w = r[3];
        *reinterpret_cast<float4*>(hp + (size_t)m * I_) = v;
    }
}

// ---------------------------------------------------------------------------
// Kernel B: out[e] = h[e] @ Wd[e]^T.  h: [T, I], Wd: [H, I], out: [T, H].
// grid = (H/64, T/128, E), block = 256. Same tiling as kernel A, single GEMM.
// ---------------------------------------------------------------------------
__global__ __launch_bounds__(256)
void moe_down_kernel(const float* __restrict__ wd,
                     float* __restrict__ out)
{
    __shared__ float Hs[32 * 132];   // [k][m]
    __shared__ float Ws[32 * 68];    // [k][n]

    const int e    = blockIdx.z;
    const int row0 = blockIdx.y * 128;   // token tile
    const int col0 = blockIdx.x * 64;    // H tile
    const int tid  = threadIdx.x;
    const int tx   = tid & 15;
    const int ty   = tid >> 4;

    const float* wd_e = wd + (size_t)e * H_ * I_;
    const float* hbuf = g_hbuf + (size_t)e * T_ * I_;

    float acc[8][4];
#pragma unroll
    for (int m = 0; m < 8; ++m)
#pragma unroll
        for (int n = 0; n < 4; ++n) acc[m][n] = 0.f;

    for (int kk = 0; kk < I_; kk += 32) {
#pragma unroll
        for (int i = tid; i < 128 * 32; i += 256) {
            int m = i >> 5, k = i & 31;
            Hs[k * 132 + m] = hbuf[(size_t)(row0 + m) * I_ + kk + k];
        }
#pragma unroll
        for (int i = tid; i < 64 * 32; i += 256) {
            int n = i >> 5, k = i & 31;
            Ws[k * 68 + n] = wd_e[(size_t)(col0 + n) * I_ + kk + k];
        }
        __syncthreads();

#pragma unroll
        for (int k = 0; k < 32; ++k) {
            float a[8], b[4];
            const float4 a0 = *reinterpret_cast<const float4*>(&Hs[k * 132 + ty * 8]);
            const float4 a1 = *reinterpret_cast<const float4*>(&Hs[k * 132 + ty * 8 + 4]);
            a[0]=a0.x; a[1]=a0.y; a[2]=a0.z; a[3]=a0.w;
            a[4]=a1.x; a[5]=a1.y; a[6]=a1.z; a[7]=a1.w;
            const float4 b4 = *reinterpret_cast<const float4*>(&Ws[k * 68 + tx * 4]);
            b[0]=b4.x; b[1]=b4.y; b[2]=b4.z; b[3]=b4.w;
#pragma unroll
            for (int m = 0; m < 8; ++m)
#pragma unroll
                for (int n = 0; n < 4; ++n)
                    acc[m][n] = fmaf(a[m], b[n], acc[m][n]);
        }
        __syncthreads();
    }

    // out is [E*T, H]
    const int row = row0 + ty * 8;
    const int col = col0 + tx * 4;
    float* op = out + ((size_t)e * T_ + row) * H_ + col;
#pragma unroll
    for (int m = 0; m < 8; ++m) {
        float4 v;
        v.x = acc[m][0]; v.y = acc[m][1]; v.z = acc[m][2]; v.w = acc[m][3];
        *reinterpret_cast<float4*>(op + (size_t)m * H_) = v;
    }
}

extern "C" void kernel_launch(void* const* d_in, const int* in_sizes, int n_in,
                              void* d_out, int out_size)
{
    const float* x  = (const float*)d_in[0];   // hidden_states [T, H]
    const float* wg = (const float*)d_in[1];   // w_gate [E, I, H]
    const float* wu = (const float*)d_in[2];   // w_up   [E, I, H]
    const float* wd = (const float*)d_in[3];   // w_down [E, H, I]
    float* out = (float*)d_out;                // [E*T, H]

    dim3 blockA(256), blockB(256);
    dim3 gridA(I_ / 64, T_ / 128, E_);   // (16, 2, 16)
    dim3 gridB(H_ / 64, T_ / 128, E_);   // (32, 2, 16)

    moe_gateup_kernel<<<gridA, blockA>>>(x, wg, wu);
    moe_down_kernel<<<gridB, blockB>>>(wd, out);
}

// round 5
// speedup vs baseline: 3.9544x; 3.9544x over previous
#include <cuda_runtime.h>
#include <cstdint>

#define E_ 16
#define T_ 256
#define H_ 2048
#define I_ 1024

// 16 MB intermediate: h[e,t,i] = silu(gate)*up (fp32)
__device__ float g_hbuf[E_ * T_ * I_];

__device__ __forceinline__ uint32_t f2tf32(float x) {
    uint32_t r;
    asm("cvt.rna.tf32.f32 %0, %1;" : "=r"(r) : "f"(x));
    return r;
}

// D += A(16x8 row) * B(8x8 col), tf32 inputs, f32 accum.
__device__ __forceinline__ void mma8(float c[4], const uint32_t a[4], const uint32_t b[2]) {
    asm volatile(
        "mma.sync.aligned.m16n8k8.row.col.f32.tf32.tf32.f32 "
        "{%0,%1,%2,%3}, {%4,%5,%6,%7}, {%8,%9}, {%0,%1,%2,%3};"
        : "+f"(c[0]), "+f"(c[1]), "+f"(c[2]), "+f"(c[3])
        : "r"(a[0]), "r"(a[1]), "r"(a[2]), "r"(a[3]), "r"(b[0]), "r"(b[1]));
}

#define PADK 36   // 32 k-floats padded to 36 (144B rows, 16B aligned, conflict-free)

// ---------------------------------------------------------------------------
// Kernel A: fused gate+up.  grid=(I/128, T/64, E), block=512.
// Block tile: 64(M) x 128(N) x 32(K). 16 warps (2m x 8n), warp tile 32x16.
// ---------------------------------------------------------------------------
__global__ __launch_bounds__(512)
void moe_gateup_mma(const float* __restrict__ x,
                    const float* __restrict__ wg,
                    const float* __restrict__ wu)
{
    extern __shared__ char smraw[];
    uint32_t* As = (uint32_t*)smraw;            // 64  x 36
    uint32_t* Gs = As + 64 * PADK;              // 128 x 36
    uint32_t* Us = Gs + 128 * PADK;             // 128 x 36

    const int tid  = threadIdx.x;
    const int e    = blockIdx.z;
    const int row0 = blockIdx.y * 64;    // token block
    const int col0 = blockIdx.x * 128;   // I block
    const int w    = tid >> 5, lane = tid & 31;
    const int gid  = lane >> 2, tg = lane & 3;
    const int m0   = (w >> 3) * 32;      // 0 or 32
    const int n0   = (w & 7) * 16;       // 0..112

    const float4* x4 = (const float4*)(x + (size_t)row0 * H_);                 // rows 0..63
    const float4* g4 = (const float4*)(wg + ((size_t)e * I_ + col0) * H_);     // rows 0..127
    const float4* u4 = (const float4*)(wu + ((size_t)e * I_ + col0) * H_);

    // prefetch mapping
    const int ra  = tid >> 3, fa = tid & 7;          // A: 512 slots, 1/thread
    const int rw0 = tid >> 3, rw1 = (tid + 512) >> 3; // W: 1024 slots, 2/thread
    const int fw  = tid & 7;

    float accg[2][2][4] = {};
    float accu[2][2][4] = {};

    float4 pA, pG0, pG1, pU0, pU1;
    pA  = x4[(size_t)ra  * 512 + fa];
    pG0 = g4[(size_t)rw0 * 512 + fw];
    pG1 = g4[(size_t)rw1 * 512 + fw];
    pU0 = u4[(size_t)rw0 * 512 + fw];
    pU1 = u4[(size_t)rw1 * 512 + fw];

    const int NCH = H_ / 32;   // 64
    for (int it = 0; it < NCH; ++it) {
        // stage (with tf32 convert)
        {
            uint32_t* d = As + ra * PADK + fa * 4;
            d[0]=f2tf32(pA.x); d[1]=f2tf32(pA.y); d[2]=f2tf32(pA.z); d[3]=f2tf32(pA.w);
            d = Gs + rw0 * PADK + fw * 4;
            d[0]=f2tf32(pG0.x); d[1]=f2tf32(pG0.y); d[2]=f2tf32(pG0.z); d[3]=f2tf32(pG0.w);
            d = Gs + rw1 * PADK + fw * 4;
            d[0]=f2tf32(pG1.x); d[1]=f2tf32(pG1.y); d[2]=f2tf32(pG1.z); d[3]=f2tf32(pG1.w);
            d = Us + rw0 * PADK + fw * 4;
            d[0]=f2tf32(pU0.x); d[1]=f2tf32(pU0.y); d[2]=f2tf32(pU0.z); d[3]=f2tf32(pU0.w);
            d = Us + rw1 * PADK + fw * 4;
            d[0]=f2tf32(pU1.x); d[1]=f2tf32(pU1.y); d[2]=f2tf32(pU1.z); d[3]=f2tf32(pU1.w);
        }
        __syncthreads();

        if (it + 1 < NCH) {   // prefetch next chunk (overlaps compute)
            const int o = (it + 1) * 8;
            pA  = x4[(size_t)ra  * 512 + o + fa];
            pG0 = g4[(size_t)rw0 * 512 + o + fw];
            pG1 = g4[(size_t)rw1 * 512 + o + fw];
            pU0 = u4[(size_t)rw0 * 512 + o + fw];
            pU1 = u4[(size_t)rw1 * 512 + o + fw];
        }

#pragma unroll
        for (int k = 0; k < 4; ++k) {
            const int k0 = k * 8;
            uint32_t a[2][4];
#pragma unroll
            for (int mt = 0; mt < 2; ++mt) {
                const int rb = (m0 + mt * 16 + gid) * PADK + k0 + tg;
                a[mt][0] = As[rb];
                a[mt][1] = As[rb + 8 * PADK];
                a[mt][2] = As[rb + 4];
                a[mt][3] = As[rb + 8 * PADK + 4];
            }
#pragma unroll
            for (int nt = 0; nt < 2; ++nt) {
                const int nb = (n0 + nt * 8 + gid) * PADK + k0 + tg;
                uint32_t bg[2] = { Gs[nb], Gs[nb + 4] };
                uint32_t bu[2] = { Us[nb], Us[nb + 4] };
                mma8(accg[0][nt], a[0], bg);
                mma8(accg[1][nt], a[1], bg);
                mma8(accu[0][nt], a[0], bu);
                mma8(accu[1][nt], a[1], bu);
            }
        }
        __syncthreads();
    }

    // epilogue: h = silu(g) * u
#pragma unroll
    for (int mt = 0; mt < 2; ++mt)
#pragma unroll
        for (int nt = 0; nt < 2; ++nt) {
            const int c = col0 + n0 + nt * 8 + tg * 2;
#pragma unroll
            for (int hh = 0; hh < 2; ++hh) {
                const int r = row0 + m0 + mt * 16 + gid + hh * 8;
                float g0 = accg[mt][nt][hh * 2 + 0], g1 = accg[mt][nt][hh * 2 + 1];
                float u0 = accu[mt][nt][hh * 2 + 0], u1 = accu[mt][nt][hh * 2 + 1];
                float2 v;
                v.x = g0 / (1.0f + __expf(-g0)) * u0;
                v.y = g1 / (1.0f + __expf(-g1)) * u1;
                *(float2*)(g_hbuf + ((size_t)e * T_ + r) * I_ + c) = v;
            }
        }
}

// ---------------------------------------------------------------------------
// Kernel B: down projection.  grid=(H/128, T/128, E), block=512.
// Block tile: 128 x 128 x 32. 16 warps (4m x 4n), warp tile 32x32.
// ---------------------------------------------------------------------------
__global__ __launch_bounds__(512)
void moe_down_mma(const float* __restrict__ wd,
                  float* __restrict__ out)
{
    extern __shared__ char smraw[];
    uint32_t* As = (uint32_t*)smraw;        // 128 x 36
    uint32_t* Bs = As + 128 * PADK;         // 128 x 36

    const int tid  = threadIdx.x;
    const int e    = blockIdx.z;
    const int row0 = blockIdx.y * 128;
    const int col0 = blockIdx.x * 128;   // H block
    const int w    = tid >> 5, lane = tid & 31;
    const int gid  = lane >> 2, tg = lane & 3;
    const int m0   = (w >> 2) * 32;
    const int n0   = (w & 3) * 32;

    const float4* h4 = (const float4*)(g_hbuf + ((size_t)e * T_ + row0) * I_);
    const float4* b4 = (const float4*)(wd + ((size_t)e * H_ + col0) * I_);

    const int r0 = tid >> 3, r1 = (tid + 512) >> 3;
    const int ff = tid & 7;

    float acc[2][4][4] = {};

    float4 pA0, pA1, pB0, pB1;
    pA0 = h4[(size_t)r0 * 256 + ff];
    pA1 = h4[(size_t)r1 * 256 + ff];
    pB0 = b4[(size_t)r0 * 256 + ff];
    pB1 = b4[(size_t)r1 * 256 + ff];

    const int NCH = I_ / 32;   // 32
    for (int it = 0; it < NCH; ++it) {
        {
            uint32_t* d = As + r0 * PADK + ff * 4;
            d[0]=f2tf32(pA0.x); d[1]=f2tf32(pA0.y); d[2]=f2tf32(pA0.z); d[3]=f2tf32(pA0.w);
            d = As + r1 * PADK + ff * 4;
            d[0]=f2tf32(pA1.x); d[1]=f2tf32(pA1.y); d[2]=f2tf32(pA1.z); d[3]=f2tf32(pA1.w);
            d = Bs + r0 * PADK + ff * 4;
            d[0]=f2tf32(pB0.x); d[1]=f2tf32(pB0.y); d[2]=f2tf32(pB0.z); d[3]=f2tf32(pB0.w);
            d = Bs + r1 * PADK + ff * 4;
            d[0]=f2tf32(pB1.x); d[1]=f2tf32(pB1.y); d[2]=f2tf32(pB1.z); d[3]=f2tf32(pB1.w);
        }
        __syncthreads();

        if (it + 1 < NCH) {
            const int o = (it + 1) * 8;
            pA0 = h4[(size_t)r0 * 256 + o + ff];
            pA1 = h4[(size_t)r1 * 256 + o + ff];
            pB0 = b4[(size_t)r0 * 256 + o + ff];
            pB1 = b4[(size_t)r1 * 256 + o + ff];
        }

#pragma unroll
        for (int k = 0; k < 4; ++k) {
            const int k0 = k * 8;
            uint32_t a[2][4];
#pragma unroll
            for (int mt = 0; mt < 2; ++mt) {
                const int rb = (m0 + mt * 16 + gid) * PADK + k0 + tg;
                a[mt][0] = As[rb];
                a[mt][1] = As[rb + 8 * PADK];
                a[mt][2] = As[rb + 4];
                a[mt][3] = As[rb + 8 * PADK + 4];
            }
#pragma unroll
            for (int nt = 0; nt < 4; ++nt) {
                const int nb = (n0 + nt * 8 + gid) * PADK + k0 + tg;
                uint32_t bb[2] = { Bs[nb], Bs[nb + 4] };
                mma8(acc[0][nt], a[0], bb);
                mma8(acc[1][nt], a[1], bb);
            }
        }
        __syncthreads();
    }

#pragma unroll
    for (int mt = 0; mt < 2; ++mt)
#pragma unroll
        for (int nt = 0; nt < 4; ++nt) {
            const int c = col0 + n0 + nt * 8 + tg * 2;
#pragma unroll
            for (int hh = 0; hh < 2; ++hh) {
                const int r = row0 + m0 + mt * 16 + gid + hh * 8;
                float2 v;
                v.x = acc[mt][nt][hh * 2 + 0];
                v.y = acc[mt][nt][hh * 2 + 1];
                *(float2*)(out + ((size_t)e * T_ + r) * H_ + c) = v;
            }
        }
}

// ---------------------------------------------------------------------------
extern "C" void kernel_launch(void* const* d_in, const int* in_sizes, int n_in,
                              void* d_out, int out_size)
{
    const float* x  = (const float*)d_in[0];   // [T, H]
    const float* wg = (const float*)d_in[1];   // [E, I, H]
    const float* wu = (const float*)d_in[2];   // [E, I, H]
    const float* wd = (const float*)d_in[3];   // [E, H, I]
    float* out = (float*)d_out;                // [E*T, H]

    const int SM1 = (64 + 128 + 128) * PADK * 4;   // 46080 B
    const int SM2 = (128 + 128) * PADK * 4;        // 36864 B
    cudaFuncSetAttribute(moe_gateup_mma, cudaFuncAttributeMaxDynamicSharedMemorySize, SM1);
    cudaFuncSetAttribute(moe_down_mma,   cudaFuncAttributeMaxDynamicSharedMemorySize, SM2);

    dim3 gridA(I_ / 128, T_ / 64, E_);    // (8, 4, 16)
    dim3 gridB(H_ / 128, T_ / 128, E_);   // (16, 2, 16)

    moe_gateup_mma<<<gridA, 512, SM1>>>(x, wg, wu);
    moe_down_mma<<<gridB, 512, SM2>>>(wd, out);
}